// round 11
// baseline (speedup 1.0000x reference)
#include <cuda_runtime.h>
#include <cuda_fp16.h>
#include <math.h>

#define NB   8
#define GH   224
#define GW   224
#define RAD  3
#define TW   16          // tile width
#define TH   32          // tile height (4 px per thread, vertical)
#define HC   22          // halo cols
#define HR   38          // halo rows
#define NHALO (HR * HC)  // 836
#define NPIX (NB * GH * GW)          // 401408
#define QW   12
#define LOG2E 1.4426950408889634f
#define NSTAGE_BLKS 784              // 14 x 7 x 8 tiles
#define NQ_BLKS     3136             // NPIX / 128
#define NBIC4_BLKS  2352             // 24*224*224 / 512

// scratch (no allocations allowed)
__device__ float g_f0[NB * 972];
__device__ __align__(16) float g_tmp[24 * 18 * 224];
__device__ __align__(16) float g_bufA[NB * 3 * GH * GW];
__device__ __align__(16) float g_bufB[NB * 3 * GH * GW];
__device__ unsigned int g_q[(size_t)4 * NPIX * QW];
__device__ int g_w2q[4 * 32 * 8];
__device__ float g_w2s[4 * 32];
__device__ float g_us[4];            // per-stage static u-scale
__device__ float4 g_lutw[224];
__device__ int4   g_luti[224];

__device__ __forceinline__ int reflect224(int v) {
    if (v < 0) v = -v;
    if (v > 223) v = 446 - v;
    return v;
}

__device__ __forceinline__ float cubw(float d) {
    d = fabsf(d);
    if (d <= 1.f) return (1.25f * d - 2.25f) * d * d + 1.f;
    if (d < 2.f)  return ((-0.75f * d + 3.75f) * d - 6.f) * d + 3.f;
    return 0.f;
}

__device__ __forceinline__ int pack4(float a, float b, float c, float d, float rs) {
    int i0 = __float2int_rn(a * rs);
    int i1 = __float2int_rn(b * rs);
    int i2 = __float2int_rn(c * rs);
    int i3 = __float2int_rn(d * rs);
    return (i0 & 255) | ((i1 & 255) << 8) | ((i2 & 255) << 16) | (i3 << 24);
}

// ---------------------------------------------------------------------------
// K_init: bicubic LUT + w2 int8 quantization + per-stage u bounds
// ---------------------------------------------------------------------------
__global__ void k_init(const float* __restrict__ w1s_, const float* __restrict__ b1s_,
                       const float* __restrict__ w2s_) {
    int tid = threadIdx.x;
    if (tid < 224) {
        float fx = (tid + 0.5f) * (18.f / 224.f) - 0.5f;
        int x0 = (int)floorf(fx);
        float tx = fx - x0;
        float4 w; int4 ix;
        w.x = cubw(tx + 1.f); w.y = cubw(tx); w.z = cubw(tx - 1.f); w.w = cubw(tx - 2.f);
        ix.x = min(max(x0 - 1, 0), 17); ix.y = min(max(x0, 0), 17);
        ix.z = min(max(x0 + 1, 0), 17); ix.w = min(max(x0 + 2, 0), 17);
        g_lutw[tid] = w; g_luti[tid] = ix;
    } else if (tid >= 256 && tid < 384) {
        int r = tid - 256;                 // stage*32 + row
        const float* row = w2s_ + r * 32;
        float mx = 1e-12f;
        #pragma unroll
        for (int k = 0; k < 32; k++) mx = fmaxf(mx, fabsf(row[k]));
        float rs = 127.f / mx;
        #pragma unroll
        for (int w = 0; w < 8; w++)
            g_w2q[r * 8 + w] = pack4(row[4 * w], row[4 * w + 1], row[4 * w + 2], row[4 * w + 3], rs);
        g_w2s[r] = mx * (1.f / 127.f);
    } else if (tid >= 384 && tid < 388) {
        int s = tid - 384;
        float ub = 0.2f;                   // gelu negative lobe bound
        for (int k = 0; k < 32; k++) {
            float bnd = fabsf(b1s_[s * 32 + k]);
            for (int c = 0; c < 3; c++) bnd += fabsf(w1s_[s * 96 + k * 3 + c]);
            ub = fmaxf(ub, bnd);
        }
        g_us[s] = ub;
    }
}

// ---------------------------------------------------------------------------
// K1: linear 1000 -> 972, one warp per output, float4 loads
// ---------------------------------------------------------------------------
__global__ void k_linear(const float* __restrict__ x, const float* __restrict__ W,
                         const float* __restrict__ bias) {
    int gw = blockIdx.x * (blockDim.x >> 5) + (threadIdx.x >> 5);
    int lane = threadIdx.x & 31;
    if (gw >= NB * 972) return;
    int b = gw / 972, j = gw % 972;
    const float4* xr = (const float4*)(x + b * 1000);
    const float4* wr = (const float4*)(W + j * 1000);
    float acc = 0.f;
    for (int k = lane; k < 250; k += 32) {
        float4 xa = xr[k], wa = wr[k];
        acc += xa.x * wa.x + xa.y * wa.y + xa.z * wa.z + xa.w * wa.w;
    }
    #pragma unroll
    for (int o = 16; o; o >>= 1) acc += __shfl_xor_sync(0xffffffffu, acc, o);
    if (lane == 0) g_f0[gw] = acc + bias[j];
}

// ---------------------------------------------------------------------------
// K2a: bicubic horizontal pass: [24][18][18] -> [24][18][224]
// ---------------------------------------------------------------------------
__global__ void k_bic1() {
    int idx = blockIdx.x * blockDim.x + threadIdx.x;
    if (idx >= 24 * 18 * 224) return;
    int xo = idx % 224;
    int r  = (idx / 224) % 18;
    int bc = idx / (224 * 18);
    float4 w = g_lutw[xo];
    int4 ix = g_luti[xo];
    const float* row = g_f0 + bc * 324 + r * 18;
    g_tmp[idx] = w.x * row[ix.x] + w.y * row[ix.y] + w.z * row[ix.z] + w.w * row[ix.w];
}

// ---------------------------------------------------------------------------
// qproj block: 128 px, int8 dp4a matvec, static u-scale.
// ---------------------------------------------------------------------------
__device__ __forceinline__ void qproj_block(
    int s, int qbid, int tid,
    const float* __restrict__ guid,
    const float* __restrict__ w1s, const float* __restrict__ b1s,
    const float* __restrict__ b2s)
{
    __shared__ float sw1[96];
    __shared__ float sb1[32];
    __shared__ float sb2[32];
    __shared__ float ssc[32];
    __shared__ int sw2q[32][8];

    if (tid < 96) sw1[tid] = w1s[s * 96 + tid];
    if (tid < 32) {
        sb1[tid] = b1s[s * 32 + tid];
        sb2[tid] = b2s[s * 32 + tid];
        ssc[tid] = g_w2s[s * 32 + tid];
    }
    {
        int r = tid >> 2, c2 = (tid & 3) * 2;
        sw2q[r][c2]     = g_w2q[(s * 32 + r) * 8 + c2];
        sw2q[r][c2 + 1] = g_w2q[(s * 32 + r) * 8 + c2 + 1];
    }
    __syncthreads();

    const float uscale = g_us[s];
    const float ru = 127.f / uscale;
    const float us_ = uscale * (1.f / 127.f);

    const int pix = qbid * 128 + tid;
    const int b = pix / (GH * GW);
    const int yx = pix % (GH * GW);
    const float* gp = guid + (size_t)b * 3 * GH * GW + yx;
    const float g0 = gp[0], g1 = gp[GH * GW], g2 = gp[2 * GH * GW];

    float u[32];
    #pragma unroll
    for (int k = 0; k < 32; k++) {
        float a = sb1[k] + sw1[k * 3] * g0 + sw1[k * 3 + 1] * g1 + sw1[k * 3 + 2] * g2;
        float c = a * (0.7978845608028654f + 0.035677408136300125f * a * a);
        float th;
        asm("tanh.approx.f32 %0, %1;" : "=f"(th) : "f"(c));
        u[k] = 0.5f * a * (1.f + th);
    }
    int uw[8];
    #pragma unroll
    for (int w = 0; w < 8; w++)
        uw[w] = pack4(u[4 * w], u[4 * w + 1], u[4 * w + 2], u[4 * w + 3], ru);

    float qf[32];
    float qmax = 1e-12f;
    #pragma unroll
    for (int j = 0; j < 32; j++) {
        int d = 0;
        #pragma unroll
        for (int i = 0; i < 8; i++) d = __dp4a(uw[i], sw2q[j][i], d);
        qf[j] = fmaf((float)d, us_ * ssc[j], sb2[j]);
        qmax = fmaxf(qmax, fabsf(qf[j]));
    }
    const float rq = 127.f / qmax;
    unsigned int ow[8];
    #pragma unroll
    for (int w = 0; w < 8; w++)
        ow[w] = (unsigned int)pack4(qf[4 * w], qf[4 * w + 1], qf[4 * w + 2], qf[4 * w + 3], rq);

    unsigned int* dst = g_q + ((size_t)s * NPIX + pix) * QW;
    *(uint4*)dst       = make_uint4(ow[0], ow[1], ow[2], ow[3]);
    *(uint4*)(dst + 4) = make_uint4(ow[4], ow[5], ow[6], ow[7]);
    dst[8] = __float_as_uint(qmax * (1.f / 127.f));
}

// ---------------------------------------------------------------------------
// K_mega: bicubic vertical (4 px/thread, blocks 0..2351) + qproj ALL 4 stages.
// Small static smem only -> high occupancy for the issue-bound qproj work.
// ---------------------------------------------------------------------------
__global__ __launch_bounds__(128) void k_mega(
    float* __restrict__ dst, const float* __restrict__ guid,
    const float* __restrict__ w1s, const float* __restrict__ b1s,
    const float* __restrict__ b2s)
{
    const int bid = blockIdx.x;
    const int tid = threadIdx.x;
    if (bid >= NBIC4_BLKS) {
        int r = bid - NBIC4_BLKS;
        qproj_block(r / NQ_BLKS, r % NQ_BLKS, tid, guid, w1s, b1s, b2s);
        return;
    }
    int idx = (bid * 128 + tid) * 4;            // 24*224*224 = 2352*512 exact
    int xo = idx % 224;                         // multiple of 4
    int yo = (idx / 224) % 224;
    int bc = idx / (224 * 224);
    float4 w = g_lutw[yo];
    int4 iy = g_luti[yo];
    const float* t = g_tmp + bc * 18 * 224 + xo;
    float4 r0 = *(const float4*)(t + iy.x * 224);
    float4 r1 = *(const float4*)(t + iy.y * 224);
    float4 r2 = *(const float4*)(t + iy.z * 224);
    float4 r3 = *(const float4*)(t + iy.w * 224);
    float4 o;
    o.x = w.x * r0.x + w.y * r1.x + w.z * r2.x + w.w * r3.x;
    o.y = w.x * r0.y + w.y * r1.y + w.z * r2.y + w.w * r3.y;
    o.z = w.x * r0.z + w.y * r1.z + w.z * r2.z + w.w * r3.z;
    o.w = w.x * r0.w + w.y * r1.w + w.z * r2.w + w.w * r3.w;
    *(float4*)(dst + idx) = o;
}

// ---------------------------------------------------------------------------
// K_stage: pure JBU stage; 4 vertical px/thread; 5 blocks/SM.
// ---------------------------------------------------------------------------
__global__ __launch_bounds__(128, 5) void k_stage(
    const float* __restrict__ src, float* __restrict__ dst,
    const float* __restrict__ temps, const float* __restrict__ sigmas, int s)
{
    extern __shared__ unsigned int shQ[];      // NHALO * 12 words
    const int tid = threadIdx.x;
    const int bid = blockIdx.x;

    const int b = bid / 98;
    const int rem = bid % 98;
    const int ty0 = (rem / 14) * TH, tx0 = (rem % 14) * TW;

    const unsigned int* qbase = g_q + (size_t)s * NPIX * QW;

    for (int hp = tid; hp < NHALO; hp += 128) {
        int yy = hp / HC, xx = hp % HC;
        int gy = reflect224(ty0 + yy - RAD);
        int gx = reflect224(tx0 + xx - RAD);
        size_t pix = (size_t)b * GH * GW + (size_t)gy * GW + gx;
        const unsigned int* qp = qbase + pix * QW;
        unsigned int* qd = shQ + hp * QW;
        *(uint4*)qd       = *(const uint4*)qp;
        *(uint4*)(qd + 4) = *(const uint4*)(qp + 4);
        const float* sp = src + (size_t)b * 3 * GH * GW + (size_t)gy * GW + gx;
        *(float4*)(qd + 8) = make_float4(sp[0], sp[GH * GW], sp[2 * GH * GW],
                                         __uint_as_float(qp[8]));
    }
    __syncthreads();

    const int ty = tid >> 4, tx = tid & 15;   // pixels (4ty + p, tx), p = 0..3

    float t = expf(temps[s]);
    t = fminf(fmaxf(t, 1e-4f), 1e4f);
    const float tl2e = t * LOG2E;

    int c[4][8];
    float pre[4];
    #pragma unroll
    for (int p = 0; p < 4; p++) {
        const unsigned int* cp = shQ + ((4 * ty + p + RAD) * HC + tx + RAD) * QW;
        *(uint4*)&c[p][0] = *(const uint4*)cp;
        *(uint4*)&c[p][4] = *(const uint4*)(cp + 4);
        pre[p] = tl2e * __uint_as_float(cp[11]);
    }

    const float sig = sigmas[s];
    const float inv2s = 1.f / (2.f * sig * sig);
    float le[7];
    #pragma unroll
    for (int i = 0; i < 7; i++) {
        float d = (i - 3) * (1.f / 3.f);
        le[i] = -d * d * inv2s * LOG2E;
    }

    float sum[4] = {0.f, 0.f, 0.f, 0.f};
    float o0[4] = {0.f, 0.f, 0.f, 0.f};
    float o1[4] = {0.f, 0.f, 0.f, 0.f};
    float o2[4] = {0.f, 0.f, 0.f, 0.f};

    #pragma unroll
    for (int dyp = 0; dyp < 10; dyp++) {
        const int r = 4 * ty + dyp;
        #pragma unroll
        for (int dx = 0; dx < 7; dx++) {
            const unsigned int* np = shQ + (r * HC + tx + dx) * QW;
            int n[8];
            *(uint4*)&n[0] = *(const uint4*)np;
            *(uint4*)&n[4] = *(const uint4*)(np + 4);
            const float4 ss = *(const float4*)(np + 8);   // src0,src1,src2,scale
            #pragma unroll
            for (int p = 0; p < 4; p++) {
                if (dyp >= p && dyp < p + 7) {
                    int d = 0;
                    #pragma unroll
                    for (int i = 0; i < 8; i++) d = __dp4a(c[p][i], n[i], d);
                    float arg = fmaf(pre[p] * ss.w, (float)d, le[dyp - p] + le[dx]);
                    float w;
                    asm("ex2.approx.f32 %0, %1;" : "=f"(w) : "f"(arg));
                    sum[p] += w;
                    o0[p] += w * ss.x;
                    o1[p] += w * ss.y;
                    o2[p] += w * ss.z;
                }
            }
        }
    }

    const int ox = tx0 + tx;
    #pragma unroll
    for (int p = 0; p < 4; p++) {
        const float inv = 1.f / fmaxf(sum[p], 1e-30f);
        const int oy = ty0 + 4 * ty + p;
        float* dp = dst + ((size_t)b * 3 * GH + oy) * GW + ox;
        dp[0]           = o0[p] * inv;
        dp[GH * GW]     = o1[p] * inv;
        dp[2 * GH * GW] = o2[p] * inv;
    }
}

// ---------------------------------------------------------------------------
extern "C" void kernel_launch(void* const* d_in, const int* in_sizes, int n_in,
                              void* d_out, int out_size) {
    const float* x      = (const float*)d_in[0];
    const float* guid   = (const float*)d_in[1];
    const float* lw     = (const float*)d_in[2];
    const float* lb     = (const float*)d_in[3];
    const float* w1s    = (const float*)d_in[4];
    const float* b1s    = (const float*)d_in[5];
    const float* w2s    = (const float*)d_in[6];
    const float* b2s    = (const float*)d_in[7];
    const float* temps  = (const float*)d_in[8];
    const float* sigmas = (const float*)d_in[9];
    float* out = (float*)d_out;

    void *pa, *pb;
    cudaGetSymbolAddress(&pa, g_bufA);
    cudaGetSymbolAddress(&pb, g_bufB);
    float* A  = (float*)pa;
    float* Bb = (float*)pb;

    const int smem = NHALO * QW * 4;   // 40128 B
    cudaFuncSetAttribute(k_stage, cudaFuncAttributeMaxDynamicSharedMemorySize, smem);

    k_init<<<1, 512>>>(w1s, b1s, w2s);
    k_linear<<<972, 256>>>(x, lw, lb);
    k_bic1<<<(24 * 18 * 224 + 255) / 256, 256>>>();
    // bicubic vertical + qproj for ALL 4 stages at high occupancy
    k_mega<<<NBIC4_BLKS + 4 * NQ_BLKS, 128>>>(A, guid, w1s, b1s, b2s);
    // pure stage launches, 5 blocks/SM
    k_stage<<<NSTAGE_BLKS, 128, smem>>>(A,  Bb,  temps, sigmas, 0);
    k_stage<<<NSTAGE_BLKS, 128, smem>>>(Bb, A,   temps, sigmas, 1);
    k_stage<<<NSTAGE_BLKS, 128, smem>>>(A,  Bb,  temps, sigmas, 2);
    k_stage<<<NSTAGE_BLKS, 128, smem>>>(Bb, out, temps, sigmas, 3);
}

// round 12
// speedup vs baseline: 1.0867x; 1.0867x over previous
#include <cuda_runtime.h>
#include <cuda_fp16.h>
#include <math.h>

#define NB   8
#define GH   224
#define GW   224
#define RAD  3
#define TW   32          // tile width
#define TH   32          // tile height (4 px per thread, vertical)
#define HC   38          // halo cols
#define HR   38          // halo rows
#define NHALO (HR * HC)  // 1444
#define NPIX (NB * GH * GW)          // 401408
#define QW   12
#define LOG2E 1.4426950408889634f
#define NSTAGE_BLKS 392              // 7 x 7 x 8 tiles
#define NQ_BLKS     1568             // NPIX / 256
#define NBIC_BLKS   1176             // 24*224*224 / 1024

// scratch (no allocations allowed)
__device__ float g_f0[NB * 972];
__device__ __align__(16) float g_tmp[24 * 18 * 224];
__device__ __align__(16) float g_bufA[NB * 3 * GH * GW];
__device__ __align__(16) float g_bufB[NB * 3 * GH * GW];
__device__ unsigned int g_q[(size_t)4 * NPIX * QW];
__device__ int g_w2q[4 * 32 * 8];
__device__ float g_w2s[4 * 32];
__device__ float g_us[4];            // per-stage static u-scale
__device__ float4 g_lutw[224];
__device__ int4   g_luti[224];

__device__ __forceinline__ int reflect224(int v) {
    if (v < 0) v = -v;
    if (v > 223) v = 446 - v;
    return v;
}

__device__ __forceinline__ float cubw(float d) {
    d = fabsf(d);
    if (d <= 1.f) return (1.25f * d - 2.25f) * d * d + 1.f;
    if (d < 2.f)  return ((-0.75f * d + 3.75f) * d - 6.f) * d + 3.f;
    return 0.f;
}

__device__ __forceinline__ int pack4(float a, float b, float c, float d, float rs) {
    int i0 = __float2int_rn(a * rs);
    int i1 = __float2int_rn(b * rs);
    int i2 = __float2int_rn(c * rs);
    int i3 = __float2int_rn(d * rs);
    return (i0 & 255) | ((i1 & 255) << 8) | ((i2 & 255) << 16) | (i3 << 24);
}

// ---------------------------------------------------------------------------
// K_init: bicubic LUT + w2 int8 quantization + per-stage u bounds
// ---------------------------------------------------------------------------
__global__ void k_init(const float* __restrict__ w1s_, const float* __restrict__ b1s_,
                       const float* __restrict__ w2s_) {
    int tid = threadIdx.x;
    if (tid < 224) {
        float fx = (tid + 0.5f) * (18.f / 224.f) - 0.5f;
        int x0 = (int)floorf(fx);
        float tx = fx - x0;
        float4 w; int4 ix;
        w.x = cubw(tx + 1.f); w.y = cubw(tx); w.z = cubw(tx - 1.f); w.w = cubw(tx - 2.f);
        ix.x = min(max(x0 - 1, 0), 17); ix.y = min(max(x0, 0), 17);
        ix.z = min(max(x0 + 1, 0), 17); ix.w = min(max(x0 + 2, 0), 17);
        g_lutw[tid] = w; g_luti[tid] = ix;
    } else if (tid >= 256 && tid < 384) {
        int r = tid - 256;                 // stage*32 + row
        const float* row = w2s_ + r * 32;
        float mx = 1e-12f;
        #pragma unroll
        for (int k = 0; k < 32; k++) mx = fmaxf(mx, fabsf(row[k]));
        float rs = 127.f / mx;
        #pragma unroll
        for (int w = 0; w < 8; w++)
            g_w2q[r * 8 + w] = pack4(row[4 * w], row[4 * w + 1], row[4 * w + 2], row[4 * w + 3], rs);
        g_w2s[r] = mx * (1.f / 127.f);
    } else if (tid >= 384 && tid < 388) {
        int s = tid - 384;
        float ub = 0.2f;                   // gelu negative lobe bound
        for (int k = 0; k < 32; k++) {
            float bnd = fabsf(b1s_[s * 32 + k]);
            for (int c = 0; c < 3; c++) bnd += fabsf(w1s_[s * 96 + k * 3 + c]);
            ub = fmaxf(ub, bnd);
        }
        g_us[s] = ub;
    }
}

// ---------------------------------------------------------------------------
// K1: linear 1000 -> 972, one warp per output, float4 loads
// ---------------------------------------------------------------------------
__global__ void k_linear(const float* __restrict__ x, const float* __restrict__ W,
                         const float* __restrict__ bias) {
    int gw = blockIdx.x * (blockDim.x >> 5) + (threadIdx.x >> 5);
    int lane = threadIdx.x & 31;
    if (gw >= NB * 972) return;
    int b = gw / 972, j = gw % 972;
    const float4* xr = (const float4*)(x + b * 1000);
    const float4* wr = (const float4*)(W + j * 1000);
    float acc = 0.f;
    for (int k = lane; k < 250; k += 32) {
        float4 xa = xr[k], wa = wr[k];
        acc += xa.x * wa.x + xa.y * wa.y + xa.z * wa.z + xa.w * wa.w;
    }
    #pragma unroll
    for (int o = 16; o; o >>= 1) acc += __shfl_xor_sync(0xffffffffu, acc, o);
    if (lane == 0) g_f0[gw] = acc + bias[j];
}

// ---------------------------------------------------------------------------
// K2a: bicubic horizontal pass: [24][18][18] -> [24][18][224]
// ---------------------------------------------------------------------------
__global__ void k_bic1() {
    int idx = blockIdx.x * blockDim.x + threadIdx.x;
    if (idx >= 24 * 18 * 224) return;
    int xo = idx % 224;
    int r  = (idx / 224) % 18;
    int bc = idx / (224 * 18);
    float4 w = g_lutw[xo];
    int4 ix = g_luti[xo];
    const float* row = g_f0 + bc * 324 + r * 18;
    g_tmp[idx] = w.x * row[ix.x] + w.y * row[ix.y] + w.z * row[ix.z] + w.w * row[ix.w];
}

// ---------------------------------------------------------------------------
// qproj block: 256 px, int8 dp4a matvec, static u-scale.
// ---------------------------------------------------------------------------
__device__ __forceinline__ void qproj_block(
    int s, int qbid, int tid,
    const float* __restrict__ guid,
    const float* __restrict__ w1s, const float* __restrict__ b1s,
    const float* __restrict__ b2s)
{
    __shared__ float sw1[96];
    __shared__ float sb1[32];
    __shared__ float sb2[32];
    __shared__ float ssc[32];
    __shared__ int sw2q[32][8];

    if (tid < 96) sw1[tid] = w1s[s * 96 + tid];
    if (tid < 32) {
        sb1[tid] = b1s[s * 32 + tid];
        sb2[tid] = b2s[s * 32 + tid];
        ssc[tid] = g_w2s[s * 32 + tid];
    }
    sw2q[tid >> 3][tid & 7] = g_w2q[(s * 32 + (tid >> 3)) * 8 + (tid & 7)];
    __syncthreads();

    const float uscale = g_us[s];
    const float ru = 127.f / uscale;
    const float us_ = uscale * (1.f / 127.f);

    const int pix = qbid * 256 + tid;
    const int b = pix / (GH * GW);
    const int yx = pix % (GH * GW);
    const float* gp = guid + (size_t)b * 3 * GH * GW + yx;
    const float g0 = gp[0], g1 = gp[GH * GW], g2 = gp[2 * GH * GW];

    float u[32];
    #pragma unroll
    for (int k = 0; k < 32; k++) {
        float a = sb1[k] + sw1[k * 3] * g0 + sw1[k * 3 + 1] * g1 + sw1[k * 3 + 2] * g2;
        float c = a * (0.7978845608028654f + 0.035677408136300125f * a * a);
        float th;
        asm("tanh.approx.f32 %0, %1;" : "=f"(th) : "f"(c));
        u[k] = 0.5f * a * (1.f + th);
    }
    int uw[8];
    #pragma unroll
    for (int w = 0; w < 8; w++)
        uw[w] = pack4(u[4 * w], u[4 * w + 1], u[4 * w + 2], u[4 * w + 3], ru);

    float qf[32];
    float qmax = 1e-12f;
    #pragma unroll
    for (int j = 0; j < 32; j++) {
        int d = 0;
        #pragma unroll
        for (int i = 0; i < 8; i++) d = __dp4a(uw[i], sw2q[j][i], d);
        qf[j] = fmaf((float)d, us_ * ssc[j], sb2[j]);
        qmax = fmaxf(qmax, fabsf(qf[j]));
    }
    const float rq = 127.f / qmax;
    unsigned int ow[8];
    #pragma unroll
    for (int w = 0; w < 8; w++)
        ow[w] = (unsigned int)pack4(qf[4 * w], qf[4 * w + 1], qf[4 * w + 2], qf[4 * w + 3], rq);

    unsigned int* dst = g_q + ((size_t)s * NPIX + pix) * QW;
    *(uint4*)dst       = make_uint4(ow[0], ow[1], ow[2], ow[3]);
    *(uint4*)(dst + 4) = make_uint4(ow[4], ow[5], ow[6], ow[7]);
    dst[8] = __float_as_uint(qmax * (1.f / 127.f));
}

// ---------------------------------------------------------------------------
// K_pre: bicubic vertical pass (4 px/thread, blocks 0..1175) + qproj stage 0.
// Small static smem -> high occupancy for the issue-bound qproj work.
// ---------------------------------------------------------------------------
__global__ __launch_bounds__(256) void k_pre(
    float* __restrict__ dst, const float* __restrict__ guid,
    const float* __restrict__ w1s, const float* __restrict__ b1s,
    const float* __restrict__ b2s)
{
    const int bid = blockIdx.x;
    const int tid = threadIdx.x;
    if (bid >= NBIC_BLKS) {
        qproj_block(0, bid - NBIC_BLKS, tid, guid, w1s, b1s, b2s);
        return;
    }
    int idx = (bid * 256 + tid) * 4;            // 24*224*224 = 1176*1024 exact
    int xo = idx % 224;
    int yo = (idx / 224) % 224;
    int bc = idx / (224 * 224);
    float4 w = g_lutw[yo];
    int4 iy = g_luti[yo];
    const float* t = g_tmp + bc * 18 * 224 + xo;
    float4 r0 = *(const float4*)(t + iy.x * 224);
    float4 r1 = *(const float4*)(t + iy.y * 224);
    float4 r2 = *(const float4*)(t + iy.z * 224);
    float4 r3 = *(const float4*)(t + iy.w * 224);
    float4 o;
    o.x = w.x * r0.x + w.y * r1.x + w.z * r2.x + w.w * r3.x;
    o.y = w.x * r0.y + w.y * r1.y + w.z * r2.y + w.w * r3.y;
    o.z = w.x * r0.z + w.y * r1.z + w.z * r2.z + w.w * r3.z;
    o.w = w.x * r0.w + w.y * r1.w + w.z * r2.w + w.w * r3.w;
    *(float4*)(dst + idx) = o;
}

// ---------------------------------------------------------------------------
// K_stage: 32x32 tile JBU (blocks 0..391, single wave at 3 blocks/SM)
//          + qproj stage s+1 (blocks 392.., backfill idle slots).
// ---------------------------------------------------------------------------
__global__ __launch_bounds__(256, 3) void k_stage(
    const float* __restrict__ src, float* __restrict__ dst,
    const float* __restrict__ guid,
    const float* __restrict__ w1s, const float* __restrict__ b1s,
    const float* __restrict__ b2s,
    const float* __restrict__ temps, const float* __restrict__ sigmas,
    int s, int nq)
{
    extern __shared__ unsigned int shQ[];      // NHALO * 12 words (stage role)
    const int tid = threadIdx.x;
    const int bid = blockIdx.x;

    if (bid >= NSTAGE_BLKS) {
        qproj_block(s + 1, bid - NSTAGE_BLKS, tid, guid, w1s, b1s, b2s);
        return;
    }

    const int b = bid / 49;
    const int rem = bid % 49;
    const int ty0 = (rem / 7) * TH, tx0 = (rem % 7) * TW;

    const unsigned int* qbase = g_q + (size_t)s * NPIX * QW;

    for (int hp = tid; hp < NHALO; hp += 256) {
        int yy = hp / HC, xx = hp % HC;
        int gy = reflect224(ty0 + yy - RAD);
        int gx = reflect224(tx0 + xx - RAD);
        size_t pix = (size_t)b * GH * GW + (size_t)gy * GW + gx;
        const unsigned int* qp = qbase + pix * QW;
        unsigned int* qd = shQ + hp * QW;
        *(uint4*)qd       = *(const uint4*)qp;
        *(uint4*)(qd + 4) = *(const uint4*)(qp + 4);
        const float* sp = src + (size_t)b * 3 * GH * GW + (size_t)gy * GW + gx;
        *(float4*)(qd + 8) = make_float4(sp[0], sp[GH * GW], sp[2 * GH * GW],
                                         __uint_as_float(qp[8]));
    }
    __syncthreads();

    const int ty = tid >> 5, tx = tid & 31;   // pixels (4ty + p, tx), p = 0..3

    float t = expf(temps[s]);
    t = fminf(fmaxf(t, 1e-4f), 1e4f);
    const float tl2e = t * LOG2E;

    int c[4][8];
    float pre[4];
    #pragma unroll
    for (int p = 0; p < 4; p++) {
        const unsigned int* cp = shQ + ((4 * ty + p + RAD) * HC + tx + RAD) * QW;
        *(uint4*)&c[p][0] = *(const uint4*)cp;
        *(uint4*)&c[p][4] = *(const uint4*)(cp + 4);
        pre[p] = tl2e * __uint_as_float(cp[11]);
    }

    const float sig = sigmas[s];
    const float inv2s = 1.f / (2.f * sig * sig);
    float le[7];
    #pragma unroll
    for (int i = 0; i < 7; i++) {
        float d = (i - 3) * (1.f / 3.f);
        le[i] = -d * d * inv2s * LOG2E;
    }

    float sum[4] = {0.f, 0.f, 0.f, 0.f};
    float o0[4] = {0.f, 0.f, 0.f, 0.f};
    float o1[4] = {0.f, 0.f, 0.f, 0.f};
    float o2[4] = {0.f, 0.f, 0.f, 0.f};

    #pragma unroll
    for (int dyp = 0; dyp < 10; dyp++) {
        const int r = 4 * ty + dyp;
        #pragma unroll
        for (int dx = 0; dx < 7; dx++) {
            const unsigned int* np = shQ + (r * HC + tx + dx) * QW;
            int n[8];
            *(uint4*)&n[0] = *(const uint4*)np;
            *(uint4*)&n[4] = *(const uint4*)(np + 4);
            const float4 ss = *(const float4*)(np + 8);   // src0,src1,src2,scale
            #pragma unroll
            for (int p = 0; p < 4; p++) {
                if (dyp >= p && dyp < p + 7) {
                    int d = 0;
                    #pragma unroll
                    for (int i = 0; i < 8; i++) d = __dp4a(c[p][i], n[i], d);
                    float arg = fmaf(pre[p] * ss.w, (float)d, le[dyp - p] + le[dx]);
                    float w;
                    asm("ex2.approx.f32 %0, %1;" : "=f"(w) : "f"(arg));
                    sum[p] += w;
                    o0[p] += w * ss.x;
                    o1[p] += w * ss.y;
                    o2[p] += w * ss.z;
                }
            }
        }
    }

    const int ox = tx0 + tx;
    #pragma unroll
    for (int p = 0; p < 4; p++) {
        const float inv = 1.f / fmaxf(sum[p], 1e-30f);
        const int oy = ty0 + 4 * ty + p;
        float* dp = dst + ((size_t)b * 3 * GH + oy) * GW + ox;
        dp[0]           = o0[p] * inv;
        dp[GH * GW]     = o1[p] * inv;
        dp[2 * GH * GW] = o2[p] * inv;
    }
}

// ---------------------------------------------------------------------------
extern "C" void kernel_launch(void* const* d_in, const int* in_sizes, int n_in,
                              void* d_out, int out_size) {
    const float* x      = (const float*)d_in[0];
    const float* guid   = (const float*)d_in[1];
    const float* lw     = (const float*)d_in[2];
    const float* lb     = (const float*)d_in[3];
    const float* w1s    = (const float*)d_in[4];
    const float* b1s    = (const float*)d_in[5];
    const float* w2s    = (const float*)d_in[6];
    const float* b2s    = (const float*)d_in[7];
    const float* temps  = (const float*)d_in[8];
    const float* sigmas = (const float*)d_in[9];
    float* out = (float*)d_out;

    void *pa, *pb;
    cudaGetSymbolAddress(&pa, g_bufA);
    cudaGetSymbolAddress(&pb, g_bufB);
    float* A  = (float*)pa;
    float* Bb = (float*)pb;

    const int smem = NHALO * QW * 4;   // 69312 B
    cudaFuncSetAttribute(k_stage, cudaFuncAttributeMaxDynamicSharedMemorySize, smem);

    k_init<<<1, 512>>>(w1s, b1s, w2s);
    k_linear<<<972, 256>>>(x, lw, lb);
    k_bic1<<<(24 * 18 * 224 + 255) / 256, 256>>>();
    // bicubic vertical + qproj(stage 0) at high occupancy
    k_pre<<<NBIC_BLKS + NQ_BLKS, 256>>>(A, guid, w1s, b1s, b2s);
    // stage s (single wave) + qproj(stage s+1) backfill
    k_stage<<<NSTAGE_BLKS + NQ_BLKS, 256, smem>>>(A,  Bb,  guid, w1s, b1s, b2s, temps, sigmas, 0, 1);
    k_stage<<<NSTAGE_BLKS + NQ_BLKS, 256, smem>>>(Bb, A,   guid, w1s, b1s, b2s, temps, sigmas, 1, 1);
    k_stage<<<NSTAGE_BLKS + NQ_BLKS, 256, smem>>>(A,  Bb,  guid, w1s, b1s, b2s, temps, sigmas, 2, 1);
    k_stage<<<NSTAGE_BLKS, 256, smem>>>(Bb, out, guid, w1s, b1s, b2s, temps, sigmas, 3, 0);
}